// round 7
// baseline (speedup 1.0000x reference)
#include <cuda_runtime.h>

// RSI fused single pass, v7. out[c] = g/(g+l) over 13-wide window of
// positive/negative relative deltas (0 when no losses in window).
//
// R6 ncu: occ 40.9% (54 regs), L1 68% (smem exchange + transpose). v7:
// neighbor p-values via shuffles (no smem exchange at all), two-pass prefix
// halves snapshot registers, smem used only for the store transpose.

#define NROWS  2048
#define NCOLS  8192
#define TPB    256
#define ITEMS  16
#define WTILE  (32 * ITEMS)      // 512 outputs per warp
#define TILE   (8 * WTILE)       // 4096 outputs per block
#define MAXW   64
#define SLOT   20                // transpose stride (conflict-free STS.128)

__global__ __launch_bounds__(TPB) void rsi_v7(
    const float* __restrict__ in,
    float* __restrict__ out,
    int out_cols)
{
    __shared__ __align__(16) float s_t[8 * SLOT * 32];   // store transpose only

    const int tid   = threadIdx.x;
    const int lane  = tid & 31;
    const int wrp   = tid >> 5;
    const int row   = blockIdx.y;
    const int wbase = blockIdx.x * TILE + wrp * WTILE;   // warp's first column
    const float* rin = in + (size_t)row * NCOLS;
    float* pw = s_t + wrp * (SLOT * 32);
    float* myslot = pw + SLOT * lane;

    const bool edge = (wbase + WTILE) >= NCOLS;          // last warp of the row

    // ---- load own 16 inputs (wbase+512 <= 8192: always in-row) ----
    const int g0 = wbase + ITEMS * lane;
    const float4 xA = *(const float4*)(rin + g0);
    const float4 xB = *(const float4*)(rin + g0 + 4);
    const float4 xC = *(const float4*)(rin + g0 + 8);
    const float4 xD = *(const float4*)(rin + g0 + 12);

    // x[g0+16]: neighbor's first x via shuffle; lane 31 loads (guarded)
    float x16 = __shfl_down_sync(0xffffffffu, xA.x, 1);
    if (lane == 31)
        x16 = (!edge) ? rin[g0 + 16] : 0.0f;

    // halo x: lanes 0..12 load x[wbase+512+lane] (zero on edge warp)
    float xe = 0.0f;
    if (lane < 13) {
        const int ge = wbase + WTILE + lane;
        xe = (ge < NCOLS) ? rin[ge] : 0.0f;
    }
    const float xen = __shfl_down_sync(0xffffffffu, xe, 1);

    // ---- own 16 p-values ----
    const float xs[17] = {xA.x, xA.y, xA.z, xA.w, xB.x, xB.y, xB.z, xB.w,
                          xC.x, xC.y, xC.z, xC.w, xD.x, xD.y, xD.z, xD.w, x16};
    float p[ITEMS];
    #pragma unroll
    for (int c = 0; c < ITEMS; ++c) {
        const float prev = xs[c];
        p[c] = (prev != 0.0f) ? __fdividef(xs[c + 1] - prev, prev) : 0.0f;
    }

    // halo p (valid on lanes 0..11; consumed by lane 31 via broadcast)
    const float pe = (xe != 0.0f) ? __fdividef(xen - xe, xe) : 0.0f;

    // ---- neighbor p-values via shuffles (no smem) ----
    float n[12];
    #pragma unroll
    for (int c = 0; c < 12; ++c) {
        const float t = __shfl_down_sync(0xffffffffu, p[c], 1);
        const float h = __shfl_sync(0xffffffffu, pe, c);
        n[c] = (lane == 31) ? h : t;
    }

    // ---- 16 sliding 13-windows, two passes of 8 (half the snapshot regs).
    // Loss prefix L is bitwise unchanged across zero-loss steps -> exact l==0.
    float qs[8], ql[8], ov4[4];

    #pragma unroll
    for (int pass = 0; pass < 2; ++pass) {
        const int j0 = pass * 8;
        float S = 0.0f, L = 0.0f;
        #pragma unroll
        for (int jj = 0; jj < 20; ++jj) {
            const int j = j0 + jj;
            if (jj < 8) { qs[jj] = S; ql[jj] = L; }
            const float v = (j < ITEMS) ? p[j] : n[j - ITEMS];
            S += v;
            L += fmaxf(-v, 0.0f);
            if (jj >= 12) {
                const int k = j - 12;              // global output index 0..15
                const float l = L - ql[jj - 12];
                const float g = (S - qs[jj - 12]) + l;
                ov4[k & 3] = (l != 0.0f) ? __fdividef(g, g + l) : 0.0f;
                if ((k & 3) == 3)
                    *(float4*)(myslot + (k - 3)) =
                        make_float4(ov4[0], ov4[1], ov4[2], ov4[3]);
            }
        }
    }
    __syncwarp();

    // ---- coalesced scalar stores from transposed smem ----
    float* rout = out + (size_t)row * out_cols;
    if (!edge && wbase + WTILE <= out_cols) {
        #pragma unroll
        for (int m = 0; m < ITEMS; ++m) {
            const int o = lane + 32 * m;
            rout[wbase + o] = pw[SLOT * (o >> 4) + (o & 15)];
        }
    } else {
        #pragma unroll
        for (int m = 0; m < ITEMS; ++m) {
            const int o = lane + 32 * m;
            const int col = wbase + o;
            if (col < out_cols)
                rout[col] = pw[SLOT * (o >> 4) + (o & 15)];
        }
    }
}

// ---- Generic fallback for unexpected window sizes ----
__global__ __launch_bounds__(TPB) void rsi_generic(
    const float* __restrict__ in,
    float* __restrict__ out,
    int out_cols, int w)
{
    __shared__ float s_in[TPB + MAXW + 1];
    __shared__ float s_g [TPB + MAXW];
    __shared__ float s_l [TPB + MAXW];

    const int row  = blockIdx.y;
    const int base = blockIdx.x * TPB;
    const float* rin = in + (size_t)row * NCOLS;

    const int need_in = TPB + w + 1;
    for (int i = threadIdx.x; i < need_in; i += TPB) {
        const int col = base + i;
        s_in[i] = (col < NCOLS) ? rin[col] : 0.0f;
    }
    __syncthreads();

    const int need_p = TPB + w;
    for (int i = threadIdx.x; i < need_p; i += TPB) {
        const float prev = s_in[i];
        const float cur  = s_in[i + 1];
        const float p = (prev != 0.0f) ? (cur - prev) / prev : 0.0f;
        s_g[i] = fmaxf(p, 0.0f);
        s_l[i] = fmaxf(-p, 0.0f);
    }
    __syncthreads();

    const int c = base + threadIdx.x;
    if (c < out_cols) {
        float g = 0.0f, l = 0.0f;
        for (int j = 0; j < w; ++j) {
            g += s_g[threadIdx.x + j];
            l += s_l[threadIdx.x + j];
        }
        out[(size_t)row * out_cols + c] = (l != 0.0f) ? g / (g + l) : 0.0f;
    }
}

extern "C" void kernel_launch(void* const* d_in, const int* in_sizes, int n_in,
                              void* d_out, int out_size)
{
    const float* in  = (const float*)d_in[0];
    float*       out = (float*)d_out;

    const int out_cols = out_size / NROWS;   // NCOLS - (window_size - 1)
    int w = NCOLS - out_cols;

    if (w == 13) {
        dim3 grid((out_cols + TILE - 1) / TILE, NROWS);
        rsi_v7<<<grid, TPB>>>(in, out, out_cols);
    } else {
        if (w < 1)    w = 1;
        if (w > MAXW) w = MAXW;
        dim3 grid((out_cols + TPB - 1) / TPB, NROWS);
        rsi_generic<<<grid, TPB>>>(in, out, out_cols, w);
    }
}

// round 8
// speedup vs baseline: 1.0598x; 1.0598x over previous
#include <cuda_runtime.h>

// RSI fused single pass, v8. out[c] = g/(g+l) over 13-wide window of
// positive/negative relative deltas (0 when no losses in window).
//
// v6 base (smem exchange, ITEMS=16, transpose stores) with register surgery:
// signed window S maintained by sliding update (kills ~12 live qs snapshot
// regs), loss window kept as prefix+snapshot for bitwise-exact l==0.
// R7 lesson applied: no shuffle exchange (SHFL lat 26 made it slower).

#define NROWS  2048
#define NCOLS  8192
#define TPB    256
#define ITEMS  16
#define WTILE  (32 * ITEMS)      // 512 outputs per warp
#define TILE   (8 * WTILE)       // 4096 outputs per block
#define MAXW   64
#define SLOT   20                // smem floats per source lane (16 data + 4 pad)
#define WREGION (SLOT * 33)      // 32 lanes + halo slot

__global__ __launch_bounds__(TPB) void rsi_v8(
    const float* __restrict__ in,
    float* __restrict__ out,
    int out_cols)
{
    __shared__ __align__(16) float s_p[8 * WREGION];

    const int tid   = threadIdx.x;
    const int lane  = tid & 31;
    const int wrp   = tid >> 5;
    const int row   = blockIdx.y;
    const int wbase = blockIdx.x * TILE + wrp * WTILE;   // warp's first column
    const float* rin = in + (size_t)row * NCOLS;
    float* pw = s_p + wrp * WREGION;
    float* myslot = pw + SLOT * lane;

    const bool edge = (wbase + WTILE) >= NCOLS;          // last warp of the row

    // ---- load own 16 inputs (wbase+512 <= 8192: always in-row) ----
    const int g0 = wbase + ITEMS * lane;
    const float4 xA = *(const float4*)(rin + g0);
    const float4 xB = *(const float4*)(rin + g0 + 4);
    const float4 xC = *(const float4*)(rin + g0 + 8);
    const float4 xD = *(const float4*)(rin + g0 + 12);

    // x[g0+16]: neighbor's first x via shuffle; lane 31 loads (guarded)
    float x16 = __shfl_down_sync(0xffffffffu, xA.x, 1);
    if (lane == 31)
        x16 = (!edge) ? rin[g0 + 16] : 0.0f;

    // halo x: lanes 0..12 load x[wbase+512+lane] (zero past row end)
    float xe = 0.0f;
    if (lane < 13) {
        const int ge = wbase + WTILE + lane;
        xe = (ge < NCOLS) ? rin[ge] : 0.0f;
    }
    const float xen = __shfl_down_sync(0xffffffffu, xe, 1);

    // ---- own 16 p-values ----
    const float xs[17] = {xA.x, xA.y, xA.z, xA.w, xB.x, xB.y, xB.z, xB.w,
                          xC.x, xC.y, xC.z, xC.w, xD.x, xD.y, xD.z, xD.w, x16};
    float p[ITEMS];
    #pragma unroll
    for (int c = 0; c < ITEMS; ++c) {
        const float prev = xs[c];
        p[c] = (prev != 0.0f) ? __fdividef(xs[c + 1] - prev, prev) : 0.0f;
    }

    // ---- publish p to warp-private smem (stride-20, conflict-free STS.128) ----
    *(float4*)(myslot)      = make_float4(p[0],  p[1],  p[2],  p[3]);
    *(float4*)(myslot + 4)  = make_float4(p[4],  p[5],  p[6],  p[7]);
    *(float4*)(myslot + 8)  = make_float4(p[8],  p[9],  p[10], p[11]);
    *(float4*)(myslot + 12) = make_float4(p[12], p[13], p[14], p[15]);
    if (lane < 12) {                                     // halo p -> slot 32
        const float pe = (xe != 0.0f) ? __fdividef(xen - xe, xe) : 0.0f;
        pw[SLOT * 32 + lane] = pe;
    }
    __syncwarp();

    // ---- fetch 12 neighbor p-values (lane 31 hits halo slot 32) ----
    const float* nb = pw + SLOT * (lane + 1);
    const float4 n0 = *(const float4*)(nb);
    const float4 n1 = *(const float4*)(nb + 4);
    const float4 n2 = *(const float4*)(nb + 8);
    __syncwarp();                                        // reads done before overwrite

    const float v[ITEMS + 12] = {
        p[0], p[1], p[2],  p[3],  p[4],  p[5],  p[6],  p[7],
        p[8], p[9], p[10], p[11], p[12], p[13], p[14], p[15],
        n0.x, n0.y, n0.z, n0.w, n1.x, n1.y, n1.z, n1.w, n2.x, n2.y, n2.z, n2.w};

    // ---- 16 sliding 13-windows.
    // L: prefix + snapshot (bitwise-exact l==0, snapshots are SSA-free).
    // S: sliding signed window (no snapshots -> ~12 fewer live registers).
    float S = 0.0f, L = 0.0f;
    float ql[ITEMS], ov4[4];
    #pragma unroll
    for (int j = 0; j < ITEMS + 12; ++j) {
        if (j < ITEMS) ql[j] = L;
        L += fmaxf(-v[j], 0.0f);
        S += (j < 13) ? v[j] : (v[j] - v[j - 13]);
        if (j >= 12) {
            const int k = j - 12;
            const float l = L - ql[k];                   // exact over window
            const float t = S + l;                       // g = S + l
            ov4[k & 3] = (l != 0.0f) ? __fdividef(t, t + l) : 0.0f;
            if ((k & 3) == 3)                            // p[] consumed, neighbors done
                *(float4*)(myslot + (k - 3)) =
                    make_float4(ov4[0], ov4[1], ov4[2], ov4[3]);
        }
    }
    __syncwarp();

    // ---- coalesced scalar stores from transposed smem ----
    float* rout = out + (size_t)row * out_cols;
    if (!edge && wbase + WTILE <= out_cols) {
        #pragma unroll
        for (int m = 0; m < ITEMS; ++m) {
            const int o = lane + 32 * m;
            rout[wbase + o] = pw[SLOT * (o >> 4) + (o & 15)];
        }
    } else {
        #pragma unroll
        for (int m = 0; m < ITEMS; ++m) {
            const int o = lane + 32 * m;
            const int col = wbase + o;
            if (col < out_cols)
                rout[col] = pw[SLOT * (o >> 4) + (o & 15)];
        }
    }
}

// ---- Generic fallback for unexpected window sizes ----
__global__ __launch_bounds__(TPB) void rsi_generic(
    const float* __restrict__ in,
    float* __restrict__ out,
    int out_cols, int w)
{
    __shared__ float s_in[TPB + MAXW + 1];
    __shared__ float s_g [TPB + MAXW];
    __shared__ float s_l [TPB + MAXW];

    const int row  = blockIdx.y;
    const int base = blockIdx.x * TPB;
    const float* rin = in + (size_t)row * NCOLS;

    const int need_in = TPB + w + 1;
    for (int i = threadIdx.x; i < need_in; i += TPB) {
        const int col = base + i;
        s_in[i] = (col < NCOLS) ? rin[col] : 0.0f;
    }
    __syncthreads();

    const int need_p = TPB + w;
    for (int i = threadIdx.x; i < need_p; i += TPB) {
        const float prev = s_in[i];
        const float cur  = s_in[i + 1];
        const float p = (prev != 0.0f) ? (cur - prev) / prev : 0.0f;
        s_g[i] = fmaxf(p, 0.0f);
        s_l[i] = fmaxf(-p, 0.0f);
    }
    __syncthreads();

    const int c = base + threadIdx.x;
    if (c < out_cols) {
        float g = 0.0f, l = 0.0f;
        for (int j = 0; j < w; ++j) {
            g += s_g[threadIdx.x + j];
            l += s_l[threadIdx.x + j];
        }
        out[(size_t)row * out_cols + c] = (l != 0.0f) ? g / (g + l) : 0.0f;
    }
}

extern "C" void kernel_launch(void* const* d_in, const int* in_sizes, int n_in,
                              void* d_out, int out_size)
{
    const float* in  = (const float*)d_in[0];
    float*       out = (float*)d_out;

    const int out_cols = out_size / NROWS;   // NCOLS - (window_size - 1)
    int w = NCOLS - out_cols;

    if (w == 13) {
        dim3 grid((out_cols + TILE - 1) / TILE, NROWS);
        rsi_v8<<<grid, TPB>>>(in, out, out_cols);
    } else {
        if (w < 1)    w = 1;
        if (w > MAXW) w = MAXW;
        dim3 grid((out_cols + TPB - 1) / TPB, NROWS);
        rsi_generic<<<grid, TPB>>>(in, out, out_cols, w);
    }
}